// round 10
// baseline (speedup 1.0000x reference)
#include <cuda_runtime.h>
#include <cuda_fp16.h>
#include <math.h>
#include <stdint.h>

// Problem constants (B=2, S=2048, H=1024, E=8, I=4096, K=2)
#define Tn 4096
#define Hd 1024
#define Id 4096
#define Ed 8

// ---------------- device scratch ----------------
__device__ int    g_count[Ed];
__device__ int    g_count2[Ed];
__device__ int    g_offset[Ed];
__device__ int    g_top_e[Tn * 2];
__device__ float  g_top_w[Tn * 2];
__device__ int    g_row_tok[Tn * 2];
__device__ int    g_tok_row[Tn * 2];
// 16B+ alignment REQUIRED: cp.async 16B / __half2 accesses trap on misalignment
__device__ __align__(256) __half g_xh[(size_t)Tn * Hd];            // 8 MB
__device__ __align__(256) __half g_hidden_h[(size_t)Tn * 2 * Id];  // 67 MB
__device__ __align__(256) float  g_down[(size_t)Tn * 2 * Hd];      // 33.5 MB

// ---------------- helpers ----------------
__device__ __forceinline__ uint32_t smem_u32(const void* p) {
    uint32_t a;
    asm("{ .reg .u64 t; cvta.to.shared.u64 t, %1; cvt.u32.u64 %0, t; }" : "=r"(a) : "l"(p));
    return a;
}
__device__ __forceinline__ uint32_t packh2(float2 f) {
    __half2 h = __floats2half2_rn(f.x, f.y);
    return *(uint32_t*)&h;
}
#define MMA_F16(c, a, b0, b1) \
    asm volatile("mma.sync.aligned.m16n8k16.row.col.f32.f16.f16.f32 " \
                 "{%0,%1,%2,%3}, {%4,%5,%6,%7}, {%8,%9}, {%0,%1,%2,%3};" \
                 : "+f"((c)[0]), "+f"((c)[1]), "+f"((c)[2]), "+f"((c)[3]) \
                 : "r"((a)[0]), "r"((a)[1]), "r"((a)[2]), "r"((a)[3]), \
                   "r"(b0), "r"(b1))
#define CP16(dst_u32, src_ptr) \
    asm volatile("cp.async.cg.shared.global [%0], [%1], 16;" :: "r"(dst_u32), "l"(src_ptr))
__device__ __forceinline__ void cp_commit() { asm volatile("cp.async.commit_group;" ::: "memory"); }
__device__ __forceinline__ void cp_wait1()  { asm volatile("cp.async.wait_group 1;" ::: "memory"); }
__device__ __forceinline__ void cp_wait0()  { asm volatile("cp.async.wait_group 0;" ::: "memory"); }

// ---------------- fp32 -> fp16 convert of x ----------------
__global__ void __launch_bounds__(256) k_cvt_x(const float* __restrict__ src) {
    int i = blockIdx.x * 256 + threadIdx.x;
    if (i >= Tn * Hd / 8) return;
    size_t base = (size_t)i * 8;
    float4 a = *(const float4*)(src + base);
    float4 b = *(const float4*)(src + base + 4);
    __half2* d = (__half2*)(g_xh + base);
    d[0] = __floats2half2_rn(a.x, a.y);
    d[1] = __floats2half2_rn(a.z, a.w);
    d[2] = __floats2half2_rn(b.x, b.y);
    d[3] = __floats2half2_rn(b.z, b.w);
}

// ---------------- init / router / scan / assign ----------------
__global__ void k_init() {
    int i = threadIdx.x;
    if (i < Ed) { g_count[i] = 0; g_count2[i] = 0; }
}

__global__ void __launch_bounds__(256) k_router(const float* __restrict__ x,
                                                const float* __restrict__ gw) {
    __shared__ float sgw[Ed * Hd];
    int tid = threadIdx.x;
    for (int i = tid; i < Ed * Hd; i += 256) sgw[i] = gw[i];
    __syncthreads();
    int warp = tid >> 5, lane = tid & 31;
    int t = blockIdx.x * 8 + warp;
    float acc[Ed];
#pragma unroll
    for (int e = 0; e < Ed; e++) acc[e] = 0.f;
    const float* xr = x + (size_t)t * Hd;
    for (int h = lane; h < Hd; h += 32) {
        float xv = xr[h];
#pragma unroll
        for (int e = 0; e < Ed; e++) acc[e] += xv * sgw[e * Hd + h];
    }
#pragma unroll
    for (int e = 0; e < Ed; e++) {
#pragma unroll
        for (int o = 16; o > 0; o >>= 1) acc[e] += __shfl_xor_sync(0xffffffffu, acc[e], o);
    }
    if (lane == 0) {
        float v0 = -1e30f; int e0 = 0;
#pragma unroll
        for (int e = 0; e < Ed; e++) if (acc[e] > v0) { v0 = acc[e]; e0 = e; }
        float v1 = -1e30f; int e1 = 0;
#pragma unroll
        for (int e = 0; e < Ed; e++) if (e != e0 && acc[e] > v1) { v1 = acc[e]; e1 = e; }
        float r  = expf(v1 - v0);
        float w0 = 1.f / (1.f + r);
        float w1 = r / (1.f + r);
        g_top_e[t * 2] = e0;  g_top_e[t * 2 + 1] = e1;
        g_top_w[t * 2] = w0;  g_top_w[t * 2 + 1] = w1;
        atomicAdd(&g_count[e0], 1);
        atomicAdd(&g_count[e1], 1);
    }
}

__global__ void k_scan() {
    int off = 0;
    for (int e = 0; e < Ed; e++) { g_offset[e] = off; off += g_count[e]; }
}

__global__ void __launch_bounds__(256) k_assign() {
    int t = blockIdx.x * 256 + threadIdx.x;
    if (t >= Tn) return;
#pragma unroll
    for (int k = 0; k < 2; k++) {
        int e   = g_top_e[t * 2 + k];
        int pos = atomicAdd(&g_count2[e], 1);
        int row = g_offset[e] + pos;
        g_row_tok[row]       = t;
        g_tok_row[t * 2 + k] = row;
    }
}

// ================= GEMM1 (fp16 MMA, fp32 weights): hidden = silu(x@wg^T)*(x@wu^T) =====
// CTA 128m x 128n, K-chunk 64. 8 warps = 2m x 4n; warp 64m x 32n DUAL.
// A fp16 rows padded to 72 halves (144B); B fp32 rows padded to 68 floats (272B).
#define G1_AB (128 * 144)                     // 18432 B (A fp16)
#define G1_BB (128 * 272)                     // 34816 B (one fp32 weight matrix)
#define G1_BUFB (G1_AB + 2 * G1_BB)           // 88064 B
#define G1_SMEM (512 + 2 * G1_BUFB)           // 176640 B
__global__ void __launch_bounds__(256) k_gemm1(const float* __restrict__ wg,
                                               const float* __restrict__ wu) {
    int e   = blockIdx.z;
    int cnt = g_count[e];
    int m0  = blockIdx.x * 128;
    if (m0 >= cnt) return;
    int off = g_offset[e];
    int n0  = blockIdx.y * 128;

    extern __shared__ char smc[];
    int* toks = (int*)smc;
    char* bufs = smc + 512;

    int tid = threadIdx.x;
    int lane = tid & 31, wid = tid >> 5;
    int warp_m = wid >> 2, warp_n = wid & 3;   // 2 x 4
    int g = lane >> 2, tig = lane & 3;

    for (int i = tid; i < 128; i += 256) {
        int m = m0 + i; if (m >= cnt) m = cnt - 1;
        toks[i] = g_row_tok[off + m];
    }
    __syncthreads();

    // A slots: 128 rows x 8 quads(16B) = 1024 -> 4/thread (gathered rows -> per-slot ptr)
    const __half* agm[4]; uint32_t aoff[4];
#pragma unroll
    for (int p = 0; p < 4; p++) {
        int idx = tid + 256 * p;
        int r = idx >> 3, q = idx & 7;
        agm[p] = g_xh + (size_t)toks[r] * Hd + q * 8;
        aoff[p] = r * 144 + q * 16;
    }
    // B slots: 128 rows x 16 quads = 2048 -> 8/thread (linear rows -> base + const deltas)
    int rB = tid >> 4, qB = tid & 15;
    const float* gbase = wg + (size_t)e * Id * Hd + (size_t)(n0 + rB) * Hd + qB * 4;
    const float* ubase = wu + (size_t)e * Id * Hd + (size_t)(n0 + rB) * Hd + qB * 4;
    uint32_t bboff = rB * 272 + qB * 16;
    uint32_t smb = smem_u32(bufs);

    float cg[4][4][4] = {}, cu[4][4][4] = {};

    // prologue: chunk 0 -> buf 0
#pragma unroll
    for (int p = 0; p < 4; p++) CP16(smb + aoff[p], agm[p]);
#pragma unroll
    for (int p = 0; p < 8; p++) {
        CP16(smb + G1_AB + bboff + p * 4352,          gbase + p * 16 * Hd);
        CP16(smb + G1_AB + G1_BB + bboff + p * 4352,  ubase + p * 16 * Hd);
    }
    cp_commit();

    const int NCH = Hd / 64;  // 16
    for (int ch = 0; ch < NCH; ch++) {
        int buf = ch & 1;
        if (ch + 1 < NCH) {
            int k0 = (ch + 1) * 64;
            uint32_t base = smb + (buf ^ 1) * G1_BUFB;
#pragma unroll
            for (int p = 0; p < 4; p++) CP16(base + aoff[p], agm[p] + k0);
#pragma unroll
            for (int p = 0; p < 8; p++) {
                CP16(base + G1_AB + bboff + p * 4352,         gbase + k0 + p * 16 * Hd);
                CP16(base + G1_AB + G1_BB + bboff + p * 4352, ubase + k0 + p * 16 * Hd);
            }
            cp_commit();
            cp_wait1();
        } else {
            cp_wait0();
        }
        __syncthreads();

        const uint32_t* A  = (const uint32_t*)(bufs + buf * G1_BUFB);             // 36 words/row
        const float2*   Bg = (const float2*)(bufs + buf * G1_BUFB + G1_AB);       // 34 f2/row
        const float2*   Bu = (const float2*)(bufs + buf * G1_BUFB + G1_AB + G1_BB);
#pragma unroll
        for (int kk = 0; kk < 4; kk++) {
            int w0 = kk * 8;
            uint32_t a[4][4];
#pragma unroll
            for (int i = 0; i < 4; i++) {
                int r = warp_m * 64 + i * 16 + g;
                a[i][0] = A[r * 36 + w0 + tig];
                a[i][1] = A[(r + 8) * 36 + w0 + tig];
                a[i][2] = A[r * 36 + w0 + tig + 4];
                a[i][3] = A[(r + 8) * 36 + w0 + tig + 4];
            }
#pragma unroll
            for (int j = 0; j < 4; j++) {
                int n = warp_n * 32 + j * 8 + g;
                uint32_t bg0 = packh2(Bg[n * 34 + w0 + tig]);
                uint32_t bg1 = packh2(Bg[n * 34 + w0 + tig + 4]);
                uint32_t bu0 = packh2(Bu[n * 34 + w0 + tig]);
                uint32_t bu1 = packh2(Bu[n * 34 + w0 + tig + 4]);
#pragma unroll
                for (int i = 0; i < 4; i++) {
                    MMA_F16(cg[i][j], a[i], bg0, bg1);
                    MMA_F16(cu[i][j], a[i], bu0, bu1);
                }
            }
        }
        __syncthreads();
    }

    // epilogue: silu(gate)*up -> g_hidden_h
#pragma unroll
    for (int i = 0; i < 4; i++) {
        int rb = m0 + warp_m * 64 + i * 16 + g;
#pragma unroll
        for (int j = 0; j < 4; j++) {
            int n = n0 + warp_n * 32 + j * 8 + 2 * tig;
            if (rb < cnt) {
                size_t base = (size_t)(off + rb) * Id + n;
                float g0 = cg[i][j][0], g1 = cg[i][j][1];
                float h0 = g0 / (1.f + expf(-g0)) * cu[i][j][0];
                float h1 = g1 / (1.f + expf(-g1)) * cu[i][j][1];
                *(__half2*)(g_hidden_h + base) = __floats2half2_rn(h0, h1);
            }
            if (rb + 8 < cnt) {
                size_t base = (size_t)(off + rb + 8) * Id + n;
                float g2 = cg[i][j][2], g3 = cg[i][j][3];
                float h2 = g2 / (1.f + expf(-g2)) * cu[i][j][2];
                float h3 = g3 / (1.f + expf(-g3)) * cu[i][j][3];
                *(__half2*)(g_hidden_h + base) = __floats2half2_rn(h2, h3);
            }
        }
    }
}

// ================= GEMM2 (fp16 MMA, fp32 wd): down = hidden @ wd^T =================
// CTA 256m x 128n, K-chunk 64. 8 warps = 4m x 2n; warp 64m x 64n.
// A fp16 256 rows x 72 halves; B fp32 128 rows x 68 floats.
#define G2_AB (256 * 144)                     // 36864 B
#define G2_BB (128 * 272)                     // 34816 B
#define G2_BUFB (G2_AB + G2_BB)               // 71680 B
#define G2_SMEM (2 * G2_BUFB)                 // 143360 B
__global__ void __launch_bounds__(256) k_gemm2(const float* __restrict__ wd) {
    int e   = blockIdx.z;
    int cnt = g_count[e];
    int m0  = blockIdx.x * 256;
    if (m0 >= cnt) return;
    int off = g_offset[e];
    int n0  = blockIdx.y * 128;

    extern __shared__ char smc[];
    char* bufs = smc;

    int tid = threadIdx.x;
    int lane = tid & 31, wid = tid >> 5;
    int warp_m = wid & 3, warp_n = wid >> 2;   // 4 x 2
    int g = lane >> 2, tig = lane & 3;

    // A slots: 256 rows x 8 quads = 2048 -> 8/thread (clamped rows -> per-slot ptr)
    const __half* agm[8]; uint32_t aoff[8];
#pragma unroll
    for (int p = 0; p < 8; p++) {
        int idx = tid + 256 * p;
        int r = idx >> 3, q = idx & 7;
        int am = m0 + r; if (am >= cnt) am = cnt - 1;
        agm[p] = g_hidden_h + (size_t)(off + am) * Id + q * 8;
        aoff[p] = r * 144 + q * 16;
    }
    // B slots: 128 rows x 16 quads = 2048 -> 8/thread (linear -> base + const deltas)
    int rB = tid >> 4, qB = tid & 15;
    const float* bbase = wd + (size_t)e * Hd * Id + (size_t)(n0 + rB) * Id + qB * 4;
    uint32_t bboff = rB * 272 + qB * 16;
    uint32_t smb = smem_u32(bufs);

    float c[4][8][4] = {};

#pragma unroll
    for (int p = 0; p < 8; p++) CP16(smb + aoff[p], agm[p]);
#pragma unroll
    for (int p = 0; p < 8; p++) CP16(smb + G2_AB + bboff + p * 4352, bbase + p * 16 * Id);
    cp_commit();

    const int NCH = Id / 64;  // 64
    for (int ch = 0; ch < NCH; ch++) {
        int buf = ch & 1;
        if (ch + 1 < NCH) {
            int k0 = (ch + 1) * 64;
            uint32_t base = smb + (buf ^ 1) * G2_BUFB;
#pragma unroll
            for (int p = 0; p < 8; p++) CP16(base + aoff[p], agm[p] + k0);
#pragma unroll
            for (int p = 0; p < 8; p++)
                CP16(base + G2_AB + bboff + p * 4352, bbase + k0 + p * 16 * Id);
            cp_commit();
            cp_wait1();
        } else {
            cp_wait0();
        }
        __syncthreads();

        const uint32_t* A = (const uint32_t*)(bufs + buf * G2_BUFB);
        const float2*   B = (const float2*)(bufs + buf * G2_BUFB + G2_AB);
#pragma unroll
        for (int kk = 0; kk < 4; kk++) {
            int w0 = kk * 8;
            uint32_t a[4][4];
#pragma unroll
            for (int i = 0; i < 4; i++) {
                int r = warp_m * 64 + i * 16 + g;
                a[i][0] = A[r * 36 + w0 + tig];
                a[i][1] = A[(r + 8) * 36 + w0 + tig];
                a[i][2] = A[r * 36 + w0 + tig + 4];
                a[i][3] = A[(r + 8) * 36 + w0 + tig + 4];
            }
#pragma unroll
            for (int j = 0; j < 8; j++) {
                int n = warp_n * 64 + j * 8 + g;
                uint32_t b0 = packh2(B[n * 34 + w0 + tig]);
                uint32_t b1 = packh2(B[n * 34 + w0 + tig + 4]);
#pragma unroll
                for (int i = 0; i < 4; i++) MMA_F16(c[i][j], a[i], b0, b1);
            }
        }
        __syncthreads();
    }

#pragma unroll
    for (int i = 0; i < 4; i++) {
        int rb = m0 + warp_m * 64 + i * 16 + g;
#pragma unroll
        for (int j = 0; j < 8; j++) {
            int n = n0 + warp_n * 64 + j * 8 + 2 * tig;
            if (rb < cnt) {
                size_t base = (size_t)(off + rb) * Hd + n;
                g_down[base]     = c[i][j][0];
                g_down[base + 1] = c[i][j][1];
            }
            if (rb + 8 < cnt) {
                size_t base = (size_t)(off + rb + 8) * Hd + n;
                g_down[base]     = c[i][j][2];
                g_down[base + 1] = c[i][j][3];
            }
        }
    }
}

// ---------------- combine ----------------
__global__ void __launch_bounds__(256) k_combine(float* __restrict__ out) {
    int idx = blockIdx.x * 256 + threadIdx.x;
    int t   = idx >> 8;
    int c4  = (idx & 255) << 2;
    int r0  = g_tok_row[t * 2];
    int r1  = g_tok_row[t * 2 + 1];
    float w0 = g_top_w[t * 2];
    float w1 = g_top_w[t * 2 + 1];
    float4 d0 = *(const float4*)(g_down + (size_t)r0 * Hd + c4);
    float4 d1 = *(const float4*)(g_down + (size_t)r1 * Hd + c4);
    float4 o;
    o.x = w0 * d0.x + w1 * d1.x;
    o.y = w0 * d0.y + w1 * d1.y;
    o.z = w0 * d0.z + w1 * d1.z;
    o.w = w0 * d0.w + w1 * d1.w;
    *(float4*)(out + (size_t)t * Hd + c4) = o;
}

// ---------------- launch ----------------
extern "C" void kernel_launch(void* const* d_in, const int* in_sizes, int n_in,
                              void* d_out, int out_size) {
    const float* x  = (const float*)d_in[0];
    const float* gw = (const float*)d_in[1];
    const float* wg = (const float*)d_in[2];
    const float* wu = (const float*)d_in[3];
    const float* wd = (const float*)d_in[4];
    float* out = (float*)d_out;

    cudaFuncSetAttribute(k_gemm1, cudaFuncAttributeMaxDynamicSharedMemorySize, G1_SMEM);
    cudaFuncSetAttribute(k_gemm2, cudaFuncAttributeMaxDynamicSharedMemorySize, G2_SMEM);

    const int xw8 = Tn * Hd / 8;
    k_cvt_x<<<(xw8 + 255) / 256, 256>>>(x);

    k_init<<<1, 32>>>();
    k_router<<<Tn / 8, 256>>>(x, gw);
    k_scan<<<1, 1>>>();
    k_assign<<<Tn / 256, 256>>>();

    dim3 g1(32, 32, Ed);   // m-tiles(128) x n-tiles(128 over I) x experts (early-exit)
    k_gemm1<<<g1, 256, G1_SMEM>>>(wg, wu);

    dim3 g2(16, 8, Ed);    // m-tiles(256) x n-tiles(128 over H) x experts (early-exit)
    k_gemm2<<<g2, 256, G2_SMEM>>>(wd);

    k_combine<<<Tn * Hd / 1024, 256>>>(out);
}

// round 11
// speedup vs baseline: 1.0156x; 1.0156x over previous
#include <cuda_runtime.h>
#include <cuda_fp16.h>
#include <math.h>
#include <stdint.h>

// Problem constants (B=2, S=2048, H=1024, E=8, I=4096, K=2)
#define Tn 4096
#define Hd 1024
#define Id 4096
#define Ed 8

// ---------------- device scratch ----------------
__device__ int    g_count[Ed];
__device__ int    g_count2[Ed];
__device__ int    g_offset[Ed];
__device__ int    g_top_e[Tn * 2];
__device__ float  g_top_w[Tn * 2];
__device__ int    g_row_tok[Tn * 2];
__device__ int    g_tok_row[Tn * 2];
// 16B+ alignment REQUIRED: cp.async 16B / __half2 accesses trap on misalignment
__device__ __align__(256) __half g_xh[(size_t)Tn * Hd];            // 8 MB
__device__ __align__(256) __half g_wgh[(size_t)Ed * Id * Hd];      // 64 MB
__device__ __align__(256) __half g_wuh[(size_t)Ed * Id * Hd];      // 64 MB
__device__ __align__(256) __half g_wdh[(size_t)Ed * Hd * Id];      // 64 MB
__device__ __align__(256) __half g_hidden_h[(size_t)Tn * 2 * Id];  // 67 MB
__device__ __align__(256) float  g_down[(size_t)Tn * 2 * Hd];      // 33.5 MB

// ---------------- helpers ----------------
__device__ __forceinline__ uint32_t smem_u32(const void* p) {
    uint32_t a;
    asm("{ .reg .u64 t; cvta.to.shared.u64 t, %1; cvt.u32.u64 %0, t; }" : "=r"(a) : "l"(p));
    return a;
}
#define MMA_F16(c, a, b0, b1) \
    asm volatile("mma.sync.aligned.m16n8k16.row.col.f32.f16.f16.f32 " \
                 "{%0,%1,%2,%3}, {%4,%5,%6,%7}, {%8,%9}, {%0,%1,%2,%3};" \
                 : "+f"((c)[0]), "+f"((c)[1]), "+f"((c)[2]), "+f"((c)[3]) \
                 : "r"((a)[0]), "r"((a)[1]), "r"((a)[2]), "r"((a)[3]), \
                   "r"(b0), "r"(b1))
#define CP16(dst_u32, src_ptr) \
    asm volatile("cp.async.cg.shared.global [%0], [%1], 16;" :: "r"(dst_u32), "l"(src_ptr))
__device__ __forceinline__ void cp_commit() { asm volatile("cp.async.commit_group;" ::: "memory"); }
__device__ __forceinline__ void cp_wait1()  { asm volatile("cp.async.wait_group 1;" ::: "memory"); }
__device__ __forceinline__ void cp_wait0()  { asm volatile("cp.async.wait_group 0;" ::: "memory"); }

// ---------------- prep: all fp32->fp16 converts + counter init, ONE launch ----------------
// blocks [0,2048): x | [2048,18432): wg | [18432,34816): wu | [34816,51200): wd
#define XB 2048
#define WB 16384
__device__ __forceinline__ void cvt8(const float* __restrict__ src,
                                     __half* __restrict__ dst, size_t i8) {
    size_t base = i8 * 8;
    float4 a = *(const float4*)(src + base);
    float4 b = *(const float4*)(src + base + 4);
    __half2* d = (__half2*)(dst + base);
    d[0] = __floats2half2_rn(a.x, a.y);
    d[1] = __floats2half2_rn(a.z, a.w);
    d[2] = __floats2half2_rn(b.x, b.y);
    d[3] = __floats2half2_rn(b.z, b.w);
}
__global__ void __launch_bounds__(256) k_prep(const float* __restrict__ x,
                                              const float* __restrict__ wg,
                                              const float* __restrict__ wu,
                                              const float* __restrict__ wd) {
    int b = blockIdx.x;
    if (b == 0 && threadIdx.x < Ed) { g_count[threadIdx.x] = 0; g_count2[threadIdx.x] = 0; }
    if (b < XB) {
        cvt8(x, g_xh, (size_t)b * 256 + threadIdx.x);
    } else if (b < XB + WB) {
        cvt8(wg, g_wgh, (size_t)(b - XB) * 256 + threadIdx.x);
    } else if (b < XB + 2 * WB) {
        cvt8(wu, g_wuh, (size_t)(b - XB - WB) * 256 + threadIdx.x);
    } else {
        cvt8(wd, g_wdh, (size_t)(b - XB - 2 * WB) * 256 + threadIdx.x);
    }
}

// ---------------- router ----------------
__global__ void __launch_bounds__(256) k_router(const float* __restrict__ x,
                                                const float* __restrict__ gw) {
    __shared__ float sgw[Ed * Hd];
    int tid = threadIdx.x;
    for (int i = tid; i < Ed * Hd; i += 256) sgw[i] = gw[i];
    __syncthreads();
    int warp = tid >> 5, lane = tid & 31;
    int t = blockIdx.x * 8 + warp;
    float acc[Ed];
#pragma unroll
    for (int e = 0; e < Ed; e++) acc[e] = 0.f;
    const float* xr = x + (size_t)t * Hd;
    for (int h = lane; h < Hd; h += 32) {
        float xv = xr[h];
#pragma unroll
        for (int e = 0; e < Ed; e++) acc[e] += xv * sgw[e * Hd + h];
    }
#pragma unroll
    for (int e = 0; e < Ed; e++) {
#pragma unroll
        for (int o = 16; o > 0; o >>= 1) acc[e] += __shfl_xor_sync(0xffffffffu, acc[e], o);
    }
    if (lane == 0) {
        float v0 = -1e30f; int e0 = 0;
#pragma unroll
        for (int e = 0; e < Ed; e++) if (acc[e] > v0) { v0 = acc[e]; e0 = e; }
        float v1 = -1e30f; int e1 = 0;
#pragma unroll
        for (int e = 0; e < Ed; e++) if (e != e0 && acc[e] > v1) { v1 = acc[e]; e1 = e; }
        float r  = expf(v1 - v0);
        float w0 = 1.f / (1.f + r);
        float w1 = r / (1.f + r);
        g_top_e[t * 2] = e0;  g_top_e[t * 2 + 1] = e1;
        g_top_w[t * 2] = w0;  g_top_w[t * 2 + 1] = w1;
        atomicAdd(&g_count[e0], 1);
        atomicAdd(&g_count[e1], 1);
    }
}

// ---------------- assign (scan folded in: per-block local prefix) ----------------
__global__ void __launch_bounds__(256) k_assign() {
    __shared__ int soff[Ed];
    if (threadIdx.x == 0) {
        int o = 0;
#pragma unroll
        for (int e = 0; e < Ed; e++) { soff[e] = o; o += g_count[e]; }
        if (blockIdx.x == 0) {
#pragma unroll
            for (int e = 0; e < Ed; e++) g_offset[e] = soff[e];
        }
    }
    __syncthreads();
    int t = blockIdx.x * 256 + threadIdx.x;
    if (t >= Tn) return;
#pragma unroll
    for (int k = 0; k < 2; k++) {
        int e   = g_top_e[t * 2 + k];
        int pos = atomicAdd(&g_count2[e], 1);
        int row = soff[e] + pos;
        g_row_tok[row]       = t;
        g_tok_row[t * 2 + k] = row;
    }
}

// ================= GEMM1 (fp16 MMA): hidden = silu(x@wg^T) * (x@wu^T) =================
// CTA 128m x 128n, K-chunk 32 halves. 8 warps = 2m x 4n; warp 64m x 32n DUAL.
// SMEM rows padded to 40 halves (80 B). Buf: A[128][40] | Bg[128][40] | Bu[128][40]
#define G1_ROWB 80
#define G1_MATB (128 * G1_ROWB)               // 10240 B per matrix
#define G1_BUFB (3 * G1_MATB)                 // 30720 B per buffer
#define G1_SMEM (512 + 2 * G1_BUFB)           // 61952 B
__global__ void __launch_bounds__(256) k_gemm1() {
    int e   = blockIdx.z;
    int cnt = g_count[e];
    int m0  = blockIdx.x * 128;
    if (m0 >= cnt) return;
    int off = g_offset[e];
    int n0  = blockIdx.y * 128;

    extern __shared__ char smc[];
    int* toks = (int*)smc;
    char* bufs = smc + 512;

    int tid = threadIdx.x;
    int lane = tid & 31, wid = tid >> 5;
    int warp_m = wid >> 2, warp_n = wid & 3;   // 2 x 4
    int g = lane >> 2, tig = lane & 3;

    for (int i = tid; i < 128; i += 256) {
        int m = m0 + i; if (m >= cnt) m = cnt - 1;
        toks[i] = g_row_tok[off + m];
    }
    __syncthreads();

    // cp.async slots: 128 rows x 4 quads(16B) = 512 per matrix; 2 per thread
    const __half* wgE = g_wgh + (size_t)e * Id * Hd;
    const __half* wuE = g_wuh + (size_t)e * Id * Hd;
    const __half* agm[2]; const __half* ggm[2]; const __half* ugm[2];
    uint32_t soff[2];
#pragma unroll
    for (int p = 0; p < 2; p++) {
        int idx = tid + 256 * p;
        int r = idx >> 2, c = idx & 3;         // quad c -> 8 halves
        agm[p] = g_xh + (size_t)toks[r] * Hd + c * 8;
        ggm[p] = wgE + (size_t)(n0 + r) * Hd + c * 8;
        ugm[p] = wuE + (size_t)(n0 + r) * Hd + c * 8;
        soff[p] = r * G1_ROWB + c * 16;
    }
    uint32_t smb = smem_u32(bufs);

    float cg[4][4][4] = {}, cu[4][4][4] = {};

    // prologue: chunk 0 -> buf 0
#pragma unroll
    for (int p = 0; p < 2; p++) {
        CP16(smb + soff[p],               agm[p]);
        CP16(smb + G1_MATB + soff[p],     ggm[p]);
        CP16(smb + 2 * G1_MATB + soff[p], ugm[p]);
    }
    cp_commit();

    const int NCH = Hd / 32;  // 32
    for (int ch = 0; ch < NCH; ch++) {
        int buf = ch & 1;
        if (ch + 1 < NCH) {
            int k0 = (ch + 1) * 32;
            uint32_t base = smb + (buf ^ 1) * G1_BUFB;
#pragma unroll
            for (int p = 0; p < 2; p++) {
                CP16(base + soff[p],               agm[p] + k0);
                CP16(base + G1_MATB + soff[p],     ggm[p] + k0);
                CP16(base + 2 * G1_MATB + soff[p], ugm[p] + k0);
            }
            cp_commit();
            cp_wait1();
        } else {
            cp_wait0();
        }
        __syncthreads();

        const uint32_t* A  = (const uint32_t*)(bufs + buf * G1_BUFB);         // 20 words/row
        const uint32_t* Bg = (const uint32_t*)(bufs + buf * G1_BUFB + G1_MATB);
        const uint32_t* Bu = (const uint32_t*)(bufs + buf * G1_BUFB + 2 * G1_MATB);
#pragma unroll
        for (int kk = 0; kk < 2; kk++) {       // two k16 steps
            int w0 = kk * 8;                   // word offset within row
            uint32_t a[4][4];
#pragma unroll
            for (int i = 0; i < 4; i++) {
                int r = warp_m * 64 + i * 16 + g;
                a[i][0] = A[r * 20 + w0 + tig];
                a[i][1] = A[(r + 8) * 20 + w0 + tig];
                a[i][2] = A[r * 20 + w0 + tig + 4];
                a[i][3] = A[(r + 8) * 20 + w0 + tig + 4];
            }
#pragma unroll
            for (int j = 0; j < 4; j++) {
                int n = warp_n * 32 + j * 8 + g;
                uint32_t bg0 = Bg[n * 20 + w0 + tig], bg1 = Bg[n * 20 + w0 + tig + 4];
                uint32_t bu0 = Bu[n * 20 + w0 + tig], bu1 = Bu[n * 20 + w0 + tig + 4];
#pragma unroll
                for (int i = 0; i < 4; i++) {
                    MMA_F16(cg[i][j], a[i], bg0, bg1);
                    MMA_F16(cu[i][j], a[i], bu0, bu1);
                }
            }
        }
        __syncthreads();
    }

    // epilogue: silu(gate)*up -> g_hidden_h
#pragma unroll
    for (int i = 0; i < 4; i++) {
        int rb = m0 + warp_m * 64 + i * 16 + g;
#pragma unroll
        for (int j = 0; j < 4; j++) {
            int n = n0 + warp_n * 32 + j * 8 + 2 * tig;
            if (rb < cnt) {
                size_t base = (size_t)(off + rb) * Id + n;
                float g0 = cg[i][j][0], g1 = cg[i][j][1];
                float h0 = g0 / (1.f + expf(-g0)) * cu[i][j][0];
                float h1 = g1 / (1.f + expf(-g1)) * cu[i][j][1];
                *(__half2*)(g_hidden_h + base) = __floats2half2_rn(h0, h1);
            }
            if (rb + 8 < cnt) {
                size_t base = (size_t)(off + rb + 8) * Id + n;
                float g2 = cg[i][j][2], g3 = cg[i][j][3];
                float h2 = g2 / (1.f + expf(-g2)) * cu[i][j][2];
                float h3 = g3 / (1.f + expf(-g3)) * cu[i][j][3];
                *(__half2*)(g_hidden_h + base) = __floats2half2_rn(h2, h3);
            }
        }
    }
}

// ================= GEMM2 (fp16 MMA): down = hidden @ wd^T =================
// CTA 256m x 128n, K-chunk 32 halves. 8 warps = 4m x 2n; warp 64m x 64n.
// Buf: A[256][40] | B[128][40]
#define G2_AB (256 * G1_ROWB)                 // 20480 B
#define G2_BB (128 * G1_ROWB)                 // 10240 B
#define G2_BUFB (G2_AB + G2_BB)               // 30720 B
#define G2_SMEM (2 * G2_BUFB)                 // 61440 B
__global__ void __launch_bounds__(256) k_gemm2() {
    int e   = blockIdx.z;
    int cnt = g_count[e];
    int m0  = blockIdx.x * 256;
    if (m0 >= cnt) return;
    int off = g_offset[e];
    int n0  = blockIdx.y * 128;

    extern __shared__ char smc[];
    char* bufs = smc;

    int tid = threadIdx.x;
    int lane = tid & 31, wid = tid >> 5;
    int warp_m = wid & 3, warp_n = wid >> 2;   // 4 x 2
    int g = lane >> 2, tig = lane & 3;

    const __half* wdE = g_wdh + (size_t)e * Hd * Id;
    // A: 256 rows x 4 quads = 1024 slots (4/thread); B: 512 slots (2/thread)
    const __half* agm[4]; uint32_t aoff[4];
    const __half* bgm[2]; uint32_t boff[2];
#pragma unroll
    for (int p = 0; p < 4; p++) {
        int idx = tid + 256 * p;
        int r = idx >> 2, c = idx & 3;
        int am = m0 + r; if (am >= cnt) am = cnt - 1;
        agm[p] = g_hidden_h + (size_t)(off + am) * Id + c * 8;
        aoff[p] = r * G1_ROWB + c * 16;
    }
#pragma unroll
    for (int p = 0; p < 2; p++) {
        int idx = tid + 256 * p;
        int r = idx >> 2, c = idx & 3;
        bgm[p] = wdE + (size_t)(n0 + r) * Id + c * 8;
        boff[p] = G2_AB + r * G1_ROWB + c * 16;
    }
    uint32_t smb = smem_u32(bufs);

    float c[4][8][4] = {};

#pragma unroll
    for (int p = 0; p < 4; p++) CP16(smb + aoff[p], agm[p]);
#pragma unroll
    for (int p = 0; p < 2; p++) CP16(smb + boff[p], bgm[p]);
    cp_commit();

    const int NCH = Id / 32;  // 128
    for (int ch = 0; ch < NCH; ch++) {
        int buf = ch & 1;
        if (ch + 1 < NCH) {
            int k0 = (ch + 1) * 32;
            uint32_t base = smb + (buf ^ 1) * G2_BUFB;
#pragma unroll
            for (int p = 0; p < 4; p++) CP16(base + aoff[p], agm[p] + k0);
#pragma unroll
            for (int p = 0; p < 2; p++) CP16(base + boff[p], bgm[p] + k0);
            cp_commit();
            cp_wait1();
        } else {
            cp_wait0();
        }
        __syncthreads();

        const uint32_t* A = (const uint32_t*)(bufs + buf * G2_BUFB);
        const uint32_t* B = (const uint32_t*)(bufs + buf * G2_BUFB + G2_AB);
#pragma unroll
        for (int kk = 0; kk < 2; kk++) {
            int w0 = kk * 8;
            uint32_t a[4][4];
#pragma unroll
            for (int i = 0; i < 4; i++) {
                int r = warp_m * 64 + i * 16 + g;
                a[i][0] = A[r * 20 + w0 + tig];
                a[i][1] = A[(r + 8) * 20 + w0 + tig];
                a[i][2] = A[r * 20 + w0 + tig + 4];
                a[i][3] = A[(r + 8) * 20 + w0 + tig + 4];
            }
#pragma unroll
            for (int j = 0; j < 8; j++) {
                int n = warp_n * 64 + j * 8 + g;
                uint32_t b0 = B[n * 20 + w0 + tig], b1 = B[n * 20 + w0 + tig + 4];
#pragma unroll
                for (int i = 0; i < 4; i++) MMA_F16(c[i][j], a[i], b0, b1);
            }
        }
        __syncthreads();
    }

#pragma unroll
    for (int i = 0; i < 4; i++) {
        int rb = m0 + warp_m * 64 + i * 16 + g;
#pragma unroll
        for (int j = 0; j < 8; j++) {
            int n = n0 + warp_n * 64 + j * 8 + 2 * tig;
            if (rb < cnt) {
                size_t base = (size_t)(off + rb) * Hd + n;
                g_down[base]     = c[i][j][0];
                g_down[base + 1] = c[i][j][1];
            }
            if (rb + 8 < cnt) {
                size_t base = (size_t)(off + rb + 8) * Hd + n;
                g_down[base]     = c[i][j][2];
                g_down[base + 1] = c[i][j][3];
            }
        }
    }
}

// ---------------- combine ----------------
__global__ void __launch_bounds__(256) k_combine(float* __restrict__ out) {
    int idx = blockIdx.x * 256 + threadIdx.x;
    int t   = idx >> 8;
    int c4  = (idx & 255) << 2;
    int r0  = g_tok_row[t * 2];
    int r1  = g_tok_row[t * 2 + 1];
    float w0 = g_top_w[t * 2];
    float w1 = g_top_w[t * 2 + 1];
    float4 d0 = *(const float4*)(g_down + (size_t)r0 * Hd + c4);
    float4 d1 = *(const float4*)(g_down + (size_t)r1 * Hd + c4);
    float4 o;
    o.x = w0 * d0.x + w1 * d1.x;
    o.y = w0 * d0.y + w1 * d1.y;
    o.z = w0 * d0.z + w1 * d1.z;
    o.w = w0 * d0.w + w1 * d1.w;
    *(float4*)(out + (size_t)t * Hd + c4) = o;
}

// ---------------- launch ----------------
extern "C" void kernel_launch(void* const* d_in, const int* in_sizes, int n_in,
                              void* d_out, int out_size) {
    const float* x  = (const float*)d_in[0];
    const float* gw = (const float*)d_in[1];
    const float* wg = (const float*)d_in[2];
    const float* wu = (const float*)d_in[3];
    const float* wd = (const float*)d_in[4];
    float* out = (float*)d_out;

    cudaFuncSetAttribute(k_gemm1, cudaFuncAttributeMaxDynamicSharedMemorySize, G1_SMEM);
    cudaFuncSetAttribute(k_gemm2, cudaFuncAttributeMaxDynamicSharedMemorySize, G2_SMEM);

    // launch 0: all converts + init (fused)
    k_prep<<<XB + 3 * WB, 256>>>(x, wg, wu, wd);
    // launch 1: router
    k_router<<<Tn / 8, 256>>>(x, gw);
    // launch 2: assign (scan folded in)
    k_assign<<<Tn / 256, 256>>>();

    // launch 3: GEMM1  (ncu profiles 0-based launch index 3)
    dim3 g1(32, 32, Ed);
    k_gemm1<<<g1, 256, G1_SMEM>>>();

    // launch 4: GEMM2
    dim3 g2(16, 8, Ed);
    k_gemm2<<<g2, 256, G2_SMEM>>>();

    // launch 5: combine
    k_combine<<<Tn * Hd / 1024, 256>>>(out);
}

// round 12
// speedup vs baseline: 1.0729x; 1.0564x over previous
#include <cuda_runtime.h>
#include <cuda_fp16.h>
#include <math.h>
#include <stdint.h>

// Problem constants (B=2, S=2048, H=1024, E=8, I=4096, K=2)
#define Tn 4096
#define Hd 1024
#define Id 4096
#define Ed 8

// ---------------- device scratch ----------------
__device__ int    g_count[Ed];
__device__ int    g_count2[Ed];
__device__ int    g_offset[Ed];
__device__ int    g_top_e[Tn * 2];
__device__ float  g_top_w[Tn * 2];
__device__ int    g_row_tok[Tn * 2];
__device__ int    g_tok_row[Tn * 2];
// 16B+ alignment REQUIRED: cp.async 16B / __half2 accesses trap on misalignment
__device__ __align__(256) __half g_xh[(size_t)Tn * Hd];            // 8 MB
__device__ __align__(256) __half g_wgh[(size_t)Ed * Id * Hd];      // 64 MB
__device__ __align__(256) __half g_wuh[(size_t)Ed * Id * Hd];      // 64 MB
__device__ __align__(256) __half g_wdh[(size_t)Ed * Hd * Id];      // 64 MB
__device__ __align__(256) __half g_hidden_h[(size_t)Tn * 2 * Id];  // 67 MB
__device__ __align__(256) float  g_down[(size_t)Tn * 2 * Hd];      // 33.5 MB

// ---------------- helpers ----------------
__device__ __forceinline__ uint32_t smem_u32(const void* p) {
    uint32_t a;
    asm("{ .reg .u64 t; cvta.to.shared.u64 t, %1; cvt.u32.u64 %0, t; }" : "=r"(a) : "l"(p));
    return a;
}
#define MMA_F16(c, a, b0, b1) \
    asm volatile("mma.sync.aligned.m16n8k16.row.col.f32.f16.f16.f32 " \
                 "{%0,%1,%2,%3}, {%4,%5,%6,%7}, {%8,%9}, {%0,%1,%2,%3};" \
                 : "+f"((c)[0]), "+f"((c)[1]), "+f"((c)[2]), "+f"((c)[3]) \
                 : "r"((a)[0]), "r"((a)[1]), "r"((a)[2]), "r"((a)[3]), \
                   "r"(b0), "r"(b1))
#define CP16(dst_u32, src_ptr) \
    asm volatile("cp.async.cg.shared.global [%0], [%1], 16;" :: "r"(dst_u32), "l"(src_ptr))
__device__ __forceinline__ void cp_commit() { asm volatile("cp.async.commit_group;" ::: "memory"); }
__device__ __forceinline__ void cp_wait1()  { asm volatile("cp.async.wait_group 1;" ::: "memory"); }
__device__ __forceinline__ void cp_wait0()  { asm volatile("cp.async.wait_group 0;" ::: "memory"); }

// ---------------- prep: all fp32->fp16 converts + counter init, ONE launch ----------------
#define XB 2048
#define WB 16384
__device__ __forceinline__ void cvt8(const float* __restrict__ src,
                                     __half* __restrict__ dst, size_t i8) {
    size_t base = i8 * 8;
    float4 a = *(const float4*)(src + base);
    float4 b = *(const float4*)(src + base + 4);
    __half2* d = (__half2*)(dst + base);
    d[0] = __floats2half2_rn(a.x, a.y);
    d[1] = __floats2half2_rn(a.z, a.w);
    d[2] = __floats2half2_rn(b.x, b.y);
    d[3] = __floats2half2_rn(b.z, b.w);
}
__global__ void __launch_bounds__(256) k_prep(const float* __restrict__ x,
                                              const float* __restrict__ wg,
                                              const float* __restrict__ wu,
                                              const float* __restrict__ wd) {
    int b = blockIdx.x;
    if (b == 0 && threadIdx.x < Ed) { g_count[threadIdx.x] = 0; g_count2[threadIdx.x] = 0; }
    if (b < XB) {
        cvt8(x, g_xh, (size_t)b * 256 + threadIdx.x);
    } else if (b < XB + WB) {
        cvt8(wg, g_wgh, (size_t)(b - XB) * 256 + threadIdx.x);
    } else if (b < XB + 2 * WB) {
        cvt8(wu, g_wuh, (size_t)(b - XB - WB) * 256 + threadIdx.x);
    } else {
        cvt8(wd, g_wdh, (size_t)(b - XB - 2 * WB) * 256 + threadIdx.x);
    }
}

// ---------------- router ----------------
__global__ void __launch_bounds__(256) k_router(const float* __restrict__ x,
                                                const float* __restrict__ gw) {
    __shared__ float sgw[Ed * Hd];
    int tid = threadIdx.x;
    for (int i = tid; i < Ed * Hd; i += 256) sgw[i] = gw[i];
    __syncthreads();
    int warp = tid >> 5, lane = tid & 31;
    int t = blockIdx.x * 8 + warp;
    float acc[Ed];
#pragma unroll
    for (int e = 0; e < Ed; e++) acc[e] = 0.f;
    const float* xr = x + (size_t)t * Hd;
    for (int h = lane; h < Hd; h += 32) {
        float xv = xr[h];
#pragma unroll
        for (int e = 0; e < Ed; e++) acc[e] += xv * sgw[e * Hd + h];
    }
#pragma unroll
    for (int e = 0; e < Ed; e++) {
#pragma unroll
        for (int o = 16; o > 0; o >>= 1) acc[e] += __shfl_xor_sync(0xffffffffu, acc[e], o);
    }
    if (lane == 0) {
        float v0 = -1e30f; int e0 = 0;
#pragma unroll
        for (int e = 0; e < Ed; e++) if (acc[e] > v0) { v0 = acc[e]; e0 = e; }
        float v1 = -1e30f; int e1 = 0;
#pragma unroll
        for (int e = 0; e < Ed; e++) if (e != e0 && acc[e] > v1) { v1 = acc[e]; e1 = e; }
        float r  = expf(v1 - v0);
        float w0 = 1.f / (1.f + r);
        float w1 = r / (1.f + r);
        g_top_e[t * 2] = e0;  g_top_e[t * 2 + 1] = e1;
        g_top_w[t * 2] = w0;  g_top_w[t * 2 + 1] = w1;
        atomicAdd(&g_count[e0], 1);
        atomicAdd(&g_count[e1], 1);
    }
}

// ---------------- assign (scan folded in) ----------------
__global__ void __launch_bounds__(256) k_assign() {
    __shared__ int soff[Ed];
    if (threadIdx.x == 0) {
        int o = 0;
#pragma unroll
        for (int e = 0; e < Ed; e++) { soff[e] = o; o += g_count[e]; }
        if (blockIdx.x == 0) {
#pragma unroll
            for (int e = 0; e < Ed; e++) g_offset[e] = soff[e];
        }
    }
    __syncthreads();
    int t = blockIdx.x * 256 + threadIdx.x;
    if (t >= Tn) return;
#pragma unroll
    for (int k = 0; k < 2; k++) {
        int e   = g_top_e[t * 2 + k];
        int pos = atomicAdd(&g_count2[e], 1);
        int row = soff[e] + pos;
        g_row_tok[row]       = t;
        g_tok_row[t * 2 + k] = row;
    }
}

// ================= GEMM1 (fp16 MMA): hidden = silu(x@wg^T) * (x@wu^T) =================
// CTA 128m x 128n, K-chunk 32 halves. 512 threads = 16 warps (4m x 4n); warp 32m x 32n DUAL.
// SMEM rows padded to 40 halves (80 B). Buf: A[128][40] | Bg[128][40] | Bu[128][40]
#define G1_ROWB 80
#define G1_MATB (128 * G1_ROWB)               // 10240 B per matrix
#define G1_BUFB (3 * G1_MATB)                 // 30720 B per buffer
#define G1_SMEM (512 + 2 * G1_BUFB)           // 61952 B
__global__ void __launch_bounds__(512) k_gemm1() {
    int e   = blockIdx.z;
    int cnt = g_count[e];
    int m0  = blockIdx.x * 128;
    if (m0 >= cnt) return;
    int off = g_offset[e];
    int n0  = blockIdx.y * 128;

    extern __shared__ char smc[];
    int* toks = (int*)smc;
    char* bufs = smc + 512;

    int tid = threadIdx.x;
    int lane = tid & 31, wid = tid >> 5;
    int warp_m = wid >> 2, warp_n = wid & 3;   // 4 x 4
    int g = lane >> 2, tig = lane & 3;

    for (int i = tid; i < 128; i += 512) {
        int m = m0 + i; if (m >= cnt) m = cnt - 1;
        toks[i] = g_row_tok[off + m];
    }
    __syncthreads();

    // cp.async slots: 128 rows x 4 quads = 512 per matrix; 1 per thread per matrix
    const __half* wgE = g_wgh + (size_t)e * Id * Hd;
    const __half* wuE = g_wuh + (size_t)e * Id * Hd;
    int rS = tid >> 2, cS = tid & 3;
    const __half* agm = g_xh + (size_t)toks[rS] * Hd + cS * 8;
    const __half* ggm = wgE + (size_t)(n0 + rS) * Hd + cS * 8;
    const __half* ugm = wuE + (size_t)(n0 + rS) * Hd + cS * 8;
    uint32_t soff = rS * G1_ROWB + cS * 16;
    uint32_t smb = smem_u32(bufs);

    float cg[2][4][4] = {}, cu[2][4][4] = {};

    // prologue: chunk 0 -> buf 0
    CP16(smb + soff,               agm);
    CP16(smb + G1_MATB + soff,     ggm);
    CP16(smb + 2 * G1_MATB + soff, ugm);
    cp_commit();

    const int NCH = Hd / 32;  // 32
    for (int ch = 0; ch < NCH; ch++) {
        int buf = ch & 1;
        if (ch + 1 < NCH) {
            int k0 = (ch + 1) * 32;
            uint32_t base = smb + (buf ^ 1) * G1_BUFB;
            CP16(base + soff,               agm + k0);
            CP16(base + G1_MATB + soff,     ggm + k0);
            CP16(base + 2 * G1_MATB + soff, ugm + k0);
            cp_commit();
            cp_wait1();
        } else {
            cp_wait0();
        }
        __syncthreads();

        const uint32_t* A  = (const uint32_t*)(bufs + buf * G1_BUFB);         // 20 words/row
        const uint32_t* Bg = (const uint32_t*)(bufs + buf * G1_BUFB + G1_MATB);
        const uint32_t* Bu = (const uint32_t*)(bufs + buf * G1_BUFB + 2 * G1_MATB);
#pragma unroll
        for (int kk = 0; kk < 2; kk++) {       // two k16 steps
            int w0 = kk * 8;
            uint32_t a[2][4];
#pragma unroll
            for (int i = 0; i < 2; i++) {
                int r = warp_m * 32 + i * 16 + g;
                a[i][0] = A[r * 20 + w0 + tig];
                a[i][1] = A[(r + 8) * 20 + w0 + tig];
                a[i][2] = A[r * 20 + w0 + tig + 4];
                a[i][3] = A[(r + 8) * 20 + w0 + tig + 4];
            }
#pragma unroll
            for (int j = 0; j < 4; j++) {
                int n = warp_n * 32 + j * 8 + g;
                uint32_t bg0 = Bg[n * 20 + w0 + tig], bg1 = Bg[n * 20 + w0 + tig + 4];
                uint32_t bu0 = Bu[n * 20 + w0 + tig], bu1 = Bu[n * 20 + w0 + tig + 4];
#pragma unroll
                for (int i = 0; i < 2; i++) {
                    MMA_F16(cg[i][j], a[i], bg0, bg1);
                    MMA_F16(cu[i][j], a[i], bu0, bu1);
                }
            }
        }
        __syncthreads();
    }

    // epilogue: silu(gate)*up -> g_hidden_h
#pragma unroll
    for (int i = 0; i < 2; i++) {
        int rb = m0 + warp_m * 32 + i * 16 + g;
#pragma unroll
        for (int j = 0; j < 4; j++) {
            int n = n0 + warp_n * 32 + j * 8 + 2 * tig;
            if (rb < cnt) {
                size_t base = (size_t)(off + rb) * Id + n;
                float g0 = cg[i][j][0], g1 = cg[i][j][1];
                float h0 = g0 / (1.f + expf(-g0)) * cu[i][j][0];
                float h1 = g1 / (1.f + expf(-g1)) * cu[i][j][1];
                *(__half2*)(g_hidden_h + base) = __floats2half2_rn(h0, h1);
            }
            if (rb + 8 < cnt) {
                size_t base = (size_t)(off + rb + 8) * Id + n;
                float g2 = cg[i][j][2], g3 = cg[i][j][3];
                float h2 = g2 / (1.f + expf(-g2)) * cu[i][j][2];
                float h3 = g3 / (1.f + expf(-g3)) * cu[i][j][3];
                *(__half2*)(g_hidden_h + base) = __floats2half2_rn(h2, h3);
            }
        }
    }
}

// ================= GEMM2 (fp16 MMA): down = hidden @ wd^T =================
// CTA 256m x 128n, K-chunk 32 halves. 512 threads = 16 warps (4m x 4n); warp 64m x 32n.
// Buf: A[256][40] | B[128][40]
#define G2_AB (256 * G1_ROWB)                 // 20480 B
#define G2_BB (128 * G1_ROWB)                 // 10240 B
#define G2_BUFB (G2_AB + G2_BB)               // 30720 B
#define G2_SMEM (2 * G2_BUFB)                 // 61440 B
__global__ void __launch_bounds__(512) k_gemm2() {
    int e   = blockIdx.z;
    int cnt = g_count[e];
    int m0  = blockIdx.x * 256;
    if (m0 >= cnt) return;
    int off = g_offset[e];
    int n0  = blockIdx.y * 128;

    extern __shared__ char smc[];
    char* bufs = smc;

    int tid = threadIdx.x;
    int lane = tid & 31, wid = tid >> 5;
    int warp_m = wid >> 2, warp_n = wid & 3;   // 4 x 4
    int g = lane >> 2, tig = lane & 3;

    const __half* wdE = g_wdh + (size_t)e * Hd * Id;
    // A: 256 rows x 4 quads = 1024 slots -> 2/thread; B: 512 slots -> 1/thread
    const __half* agm[2]; uint32_t aoff[2];
#pragma unroll
    for (int p = 0; p < 2; p++) {
        int idx = tid + 512 * p;
        int r = idx >> 2, c = idx & 3;
        int am = m0 + r; if (am >= cnt) am = cnt - 1;
        agm[p] = g_hidden_h + (size_t)(off + am) * Id + c * 8;
        aoff[p] = r * G1_ROWB + c * 16;
    }
    int rB = tid >> 2, cB = tid & 3;
    const __half* bgm = wdE + (size_t)(n0 + rB) * Id + cB * 8;
    uint32_t boff = G2_AB + rB * G1_ROWB + cB * 16;
    uint32_t smb = smem_u32(bufs);

    float c[4][4][4] = {};

#pragma unroll
    for (int p = 0; p < 2; p++) CP16(smb + aoff[p], agm[p]);
    CP16(smb + boff, bgm);
    cp_commit();

    const int NCH = Id / 32;  // 128
    for (int ch = 0; ch < NCH; ch++) {
        int buf = ch & 1;
        if (ch + 1 < NCH) {
            int k0 = (ch + 1) * 32;
            uint32_t base = smb + (buf ^ 1) * G2_BUFB;
#pragma unroll
            for (int p = 0; p < 2; p++) CP16(base + aoff[p], agm[p] + k0);
            CP16(base + boff, bgm + k0);
            cp_commit();
            cp_wait1();
        } else {
            cp_wait0();
        }
        __syncthreads();

        const uint32_t* A = (const uint32_t*)(bufs + buf * G2_BUFB);
        const uint32_t* B = (const uint32_t*)(bufs + buf * G2_BUFB + G2_AB);
#pragma unroll
        for (int kk = 0; kk < 2; kk++) {
            int w0 = kk * 8;
            uint32_t a[4][4];
#pragma unroll
            for (int i = 0; i < 4; i++) {
                int r = warp_m * 64 + i * 16 + g;
                a[i][0] = A[r * 20 + w0 + tig];
                a[i][1] = A[(r + 8) * 20 + w0 + tig];
                a[i][2] = A[r * 20 + w0 + tig + 4];
                a[i][3] = A[(r + 8) * 20 + w0 + tig + 4];
            }
#pragma unroll
            for (int j = 0; j < 4; j++) {
                int n = warp_n * 32 + j * 8 + g;
                uint32_t b0 = B[n * 20 + w0 + tig], b1 = B[n * 20 + w0 + tig + 4];
#pragma unroll
                for (int i = 0; i < 4; i++) MMA_F16(c[i][j], a[i], b0, b1);
            }
        }
        __syncthreads();
    }

#pragma unroll
    for (int i = 0; i < 4; i++) {
        int rb = m0 + warp_m * 64 + i * 16 + g;
#pragma unroll
        for (int j = 0; j < 4; j++) {
            int n = n0 + warp_n * 32 + j * 8 + 2 * tig;
            if (rb < cnt) {
                size_t base = (size_t)(off + rb) * Hd + n;
                g_down[base]     = c[i][j][0];
                g_down[base + 1] = c[i][j][1];
            }
            if (rb + 8 < cnt) {
                size_t base = (size_t)(off + rb + 8) * Hd + n;
                g_down[base]     = c[i][j][2];
                g_down[base + 1] = c[i][j][3];
            }
        }
    }
}

// ---------------- combine ----------------
__global__ void __launch_bounds__(256) k_combine(float* __restrict__ out) {
    int idx = blockIdx.x * 256 + threadIdx.x;
    int t   = idx >> 8;
    int c4  = (idx & 255) << 2;
    int r0  = g_tok_row[t * 2];
    int r1  = g_tok_row[t * 2 + 1];
    float w0 = g_top_w[t * 2];
    float w1 = g_top_w[t * 2 + 1];
    float4 d0 = *(const float4*)(g_down + (size_t)r0 * Hd + c4);
    float4 d1 = *(const float4*)(g_down + (size_t)r1 * Hd + c4);
    float4 o;
    o.x = w0 * d0.x + w1 * d1.x;
    o.y = w0 * d0.y + w1 * d1.y;
    o.z = w0 * d0.z + w1 * d1.z;
    o.w = w0 * d0.w + w1 * d1.w;
    *(float4*)(out + (size_t)t * Hd + c4) = o;
}

// ---------------- launch ----------------
extern "C" void kernel_launch(void* const* d_in, const int* in_sizes, int n_in,
                              void* d_out, int out_size) {
    const float* x  = (const float*)d_in[0];
    const float* gw = (const float*)d_in[1];
    const float* wg = (const float*)d_in[2];
    const float* wu = (const float*)d_in[3];
    const float* wd = (const float*)d_in[4];
    float* out = (float*)d_out;

    cudaFuncSetAttribute(k_gemm1, cudaFuncAttributeMaxDynamicSharedMemorySize, G1_SMEM);
    cudaFuncSetAttribute(k_gemm2, cudaFuncAttributeMaxDynamicSharedMemorySize, G2_SMEM);

    // launch 0: converts + init
    k_prep<<<XB + 3 * WB, 256>>>(x, wg, wu, wd);
    // launch 1: router
    k_router<<<Tn / 8, 256>>>(x, gw);
    // launch 2: assign
    k_assign<<<Tn / 256, 256>>>();

    // launch 3: GEMM1 (ncu profiles launch index 3)
    dim3 g1(32, 32, Ed);
    k_gemm1<<<g1, 512, G1_SMEM>>>();

    // launch 4: GEMM2
    dim3 g2(16, 8, Ed);
    k_gemm2<<<g2, 512, G2_SMEM>>>();

    // launch 5: combine
    k_combine<<<Tn * Hd / 1024, 256>>>(out);
}

// round 13
// speedup vs baseline: 1.1545x; 1.0761x over previous
#include <cuda_runtime.h>
#include <cuda_fp16.h>
#include <math.h>
#include <stdint.h>

// Problem constants (B=2, S=2048, H=1024, E=8, I=4096, K=2)
#define Tn 4096
#define Hd 1024
#define Id 4096
#define Ed 8

// ---------------- device scratch ----------------
__device__ int    g_count[Ed];
__device__ int    g_count2[Ed];
__device__ int    g_offset[Ed];
__device__ int    g_top_e[Tn * 2];
__device__ float  g_top_w[Tn * 2];
__device__ int    g_row_tok[Tn * 2];
__device__ int    g_tok_row[Tn * 2];
// 16B+ alignment REQUIRED: cp.async 16B / __half2 accesses trap on misalignment
__device__ __align__(256) __half g_xh[(size_t)Tn * Hd];            // 8 MB
__device__ __align__(256) __half g_wgh[(size_t)Ed * Id * Hd];      // 64 MB
__device__ __align__(256) __half g_wuh[(size_t)Ed * Id * Hd];      // 64 MB
__device__ __align__(256) __half g_wdh[(size_t)Ed * Hd * Id];      // 64 MB
__device__ __align__(256) __half g_hidden_h[(size_t)Tn * 2 * Id];  // 67 MB
__device__ __align__(256) float  g_down[(size_t)Tn * 2 * Hd];      // 33.5 MB

// ---------------- helpers ----------------
__device__ __forceinline__ uint32_t smem_u32(const void* p) {
    uint32_t a;
    asm("{ .reg .u64 t; cvta.to.shared.u64 t, %1; cvt.u32.u64 %0, t; }" : "=r"(a) : "l"(p));
    return a;
}
#define MMA_F16(c, a, b0, b1) \
    asm volatile("mma.sync.aligned.m16n8k16.row.col.f32.f16.f16.f32 " \
                 "{%0,%1,%2,%3}, {%4,%5,%6,%7}, {%8,%9}, {%0,%1,%2,%3};" \
                 : "+f"((c)[0]), "+f"((c)[1]), "+f"((c)[2]), "+f"((c)[3]) \
                 : "r"((a)[0]), "r"((a)[1]), "r"((a)[2]), "r"((a)[3]), \
                   "r"(b0), "r"(b1))
#define CP16(dst_u32, src_ptr) \
    asm volatile("cp.async.cg.shared.global [%0], [%1], 16;" :: "r"(dst_u32), "l"(src_ptr))
__device__ __forceinline__ void cp_commit() { asm volatile("cp.async.commit_group;" ::: "memory"); }
__device__ __forceinline__ void cp_wait1()  { asm volatile("cp.async.wait_group 1;" ::: "memory"); }
__device__ __forceinline__ void cp_wait0()  { asm volatile("cp.async.wait_group 0;" ::: "memory"); }

// ---------------- prep: all fp32->fp16 converts + counter init, ONE launch ----------------
#define XB 2048
#define WB 16384
__device__ __forceinline__ void cvt8(const float* __restrict__ src,
                                     __half* __restrict__ dst, size_t i8) {
    size_t base = i8 * 8;
    float4 a = *(const float4*)(src + base);
    float4 b = *(const float4*)(src + base + 4);
    __half2* d = (__half2*)(dst + base);
    d[0] = __floats2half2_rn(a.x, a.y);
    d[1] = __floats2half2_rn(a.z, a.w);
    d[2] = __floats2half2_rn(b.x, b.y);
    d[3] = __floats2half2_rn(b.z, b.w);
}
__global__ void __launch_bounds__(256) k_prep(const float* __restrict__ x,
                                              const float* __restrict__ wg,
                                              const float* __restrict__ wu,
                                              const float* __restrict__ wd) {
    int b = blockIdx.x;
    if (b == 0 && threadIdx.x < Ed) { g_count[threadIdx.x] = 0; g_count2[threadIdx.x] = 0; }
    if (b < XB) {
        cvt8(x, g_xh, (size_t)b * 256 + threadIdx.x);
    } else if (b < XB + WB) {
        cvt8(wg, g_wgh, (size_t)(b - XB) * 256 + threadIdx.x);
    } else if (b < XB + 2 * WB) {
        cvt8(wu, g_wuh, (size_t)(b - XB - WB) * 256 + threadIdx.x);
    } else {
        cvt8(wd, g_wdh, (size_t)(b - XB - 2 * WB) * 256 + threadIdx.x);
    }
}

// ---------------- router ----------------
__global__ void __launch_bounds__(256) k_router(const float* __restrict__ x,
                                                const float* __restrict__ gw) {
    __shared__ float sgw[Ed * Hd];
    int tid = threadIdx.x;
    for (int i = tid; i < Ed * Hd; i += 256) sgw[i] = gw[i];
    __syncthreads();
    int warp = tid >> 5, lane = tid & 31;
    int t = blockIdx.x * 8 + warp;
    float acc[Ed];
#pragma unroll
    for (int e = 0; e < Ed; e++) acc[e] = 0.f;
    const float* xr = x + (size_t)t * Hd;
    for (int h = lane; h < Hd; h += 32) {
        float xv = xr[h];
#pragma unroll
        for (int e = 0; e < Ed; e++) acc[e] += xv * sgw[e * Hd + h];
    }
#pragma unroll
    for (int e = 0; e < Ed; e++) {
#pragma unroll
        for (int o = 16; o > 0; o >>= 1) acc[e] += __shfl_xor_sync(0xffffffffu, acc[e], o);
    }
    if (lane == 0) {
        float v0 = -1e30f; int e0 = 0;
#pragma unroll
        for (int e = 0; e < Ed; e++) if (acc[e] > v0) { v0 = acc[e]; e0 = e; }
        float v1 = -1e30f; int e1 = 0;
#pragma unroll
        for (int e = 0; e < Ed; e++) if (e != e0 && acc[e] > v1) { v1 = acc[e]; e1 = e; }
        float r  = expf(v1 - v0);
        float w0 = 1.f / (1.f + r);
        float w1 = r / (1.f + r);
        g_top_e[t * 2] = e0;  g_top_e[t * 2 + 1] = e1;
        g_top_w[t * 2] = w0;  g_top_w[t * 2 + 1] = w1;
        atomicAdd(&g_count[e0], 1);
        atomicAdd(&g_count[e1], 1);
    }
}

// ---------------- assign (scan folded in) ----------------
__global__ void __launch_bounds__(256) k_assign() {
    __shared__ int soff[Ed];
    if (threadIdx.x == 0) {
        int o = 0;
#pragma unroll
        for (int e = 0; e < Ed; e++) { soff[e] = o; o += g_count[e]; }
        if (blockIdx.x == 0) {
#pragma unroll
            for (int e = 0; e < Ed; e++) g_offset[e] = soff[e];
        }
    }
    __syncthreads();
    int t = blockIdx.x * 256 + threadIdx.x;
    if (t >= Tn) return;
#pragma unroll
    for (int k = 0; k < 2; k++) {
        int e   = g_top_e[t * 2 + k];
        int pos = atomicAdd(&g_count2[e], 1);
        int row = soff[e] + pos;
        g_row_tok[row]       = t;
        g_tok_row[t * 2 + k] = row;
    }
}

// ================= GEMM1 (fp16 MMA): hidden = silu(x@wg^T) * (x@wu^T) =================
// CTA 64m x 128n, K-chunk 64 halves. 512 threads = 16 warps (2m x 8n); warp 32m x 16n DUAL.
// 2 CTAs/SM target. SMEM rows: 64 halves padded to 72 (144 B = 36 words).
#define ROWB 144
#define G1_AB (64 * ROWB)                     // 9216 B  (A: 64 rows)
#define G1_BB (128 * ROWB)                    // 18432 B (Bg / Bu: 128 rows)
#define G1_BUFB (G1_AB + 2 * G1_BB)           // 46080 B
#define G1_SMEM (512 + 2 * G1_BUFB)           // 92672 B
__global__ void __launch_bounds__(512, 2) k_gemm1() {
    int e   = blockIdx.z;
    int cnt = g_count[e];
    int m0  = blockIdx.x * 64;
    if (m0 >= cnt) return;
    int off = g_offset[e];
    int n0  = blockIdx.y * 128;

    extern __shared__ char smc[];
    int* toks = (int*)smc;
    char* bufs = smc + 512;

    int tid = threadIdx.x;
    int lane = tid & 31, wid = tid >> 5;
    int warp_m = wid >> 3, warp_n = wid & 7;   // 2 x 8
    int g = lane >> 2, tig = lane & 3;

    if (tid < 64) {
        int m = m0 + tid; if (m >= cnt) m = cnt - 1;
        toks[tid] = g_row_tok[off + m];
    }
    __syncthreads();

    // cp.async slots (16B quads, 8 per row of 128B data): A 64x8=512 (1/thr);
    // Bg,Bu 128x8=1024 each (2/thr each)
    const __half* wgE = g_wgh + (size_t)e * Id * Hd;
    const __half* wuE = g_wuh + (size_t)e * Id * Hd;
    int rA = tid >> 3, qA = tid & 7;
    const __half* agm = g_xh + (size_t)toks[rA] * Hd + qA * 8;
    uint32_t aoff = rA * ROWB + qA * 16;
    const __half* ggm[2]; const __half* ugm[2]; uint32_t boff[2];
#pragma unroll
    for (int p = 0; p < 2; p++) {
        int idx = tid + 512 * p;
        int r = idx >> 3, q = idx & 7;
        ggm[p] = wgE + (size_t)(n0 + r) * Hd + q * 8;
        ugm[p] = wuE + (size_t)(n0 + r) * Hd + q * 8;
        boff[p] = r * ROWB + q * 16;
    }
    uint32_t smb = smem_u32(bufs);

    float cg[2][2][4] = {}, cu[2][2][4] = {};

    // prologue: chunk 0 -> buf 0
    CP16(smb + aoff, agm);
#pragma unroll
    for (int p = 0; p < 2; p++) {
        CP16(smb + G1_AB + boff[p],          ggm[p]);
        CP16(smb + G1_AB + G1_BB + boff[p],  ugm[p]);
    }
    cp_commit();

    const int NCH = Hd / 64;  // 16
    for (int ch = 0; ch < NCH; ch++) {
        int buf = ch & 1;
        if (ch + 1 < NCH) {
            int k0 = (ch + 1) * 64;
            uint32_t base = smb + (buf ^ 1) * G1_BUFB;
            CP16(base + aoff, agm + k0);
#pragma unroll
            for (int p = 0; p < 2; p++) {
                CP16(base + G1_AB + boff[p],         ggm[p] + k0);
                CP16(base + G1_AB + G1_BB + boff[p], ugm[p] + k0);
            }
            cp_commit();
            cp_wait1();
        } else {
            cp_wait0();
        }
        __syncthreads();

        const uint32_t* A  = (const uint32_t*)(bufs + buf * G1_BUFB);           // 36 w/row
        const uint32_t* Bg = (const uint32_t*)(bufs + buf * G1_BUFB + G1_AB);
        const uint32_t* Bu = (const uint32_t*)(bufs + buf * G1_BUFB + G1_AB + G1_BB);
#pragma unroll
        for (int kk = 0; kk < 4; kk++) {       // four k16 steps
            int w0 = kk * 8;
            uint32_t a[2][4];
#pragma unroll
            for (int i = 0; i < 2; i++) {
                int r = warp_m * 32 + i * 16 + g;
                a[i][0] = A[r * 36 + w0 + tig];
                a[i][1] = A[(r + 8) * 36 + w0 + tig];
                a[i][2] = A[r * 36 + w0 + tig + 4];
                a[i][3] = A[(r + 8) * 36 + w0 + tig + 4];
            }
#pragma unroll
            for (int j = 0; j < 2; j++) {
                int n = warp_n * 16 + j * 8 + g;
                uint32_t bg0 = Bg[n * 36 + w0 + tig], bg1 = Bg[n * 36 + w0 + tig + 4];
                uint32_t bu0 = Bu[n * 36 + w0 + tig], bu1 = Bu[n * 36 + w0 + tig + 4];
#pragma unroll
                for (int i = 0; i < 2; i++) {
                    MMA_F16(cg[i][j], a[i], bg0, bg1);
                    MMA_F16(cu[i][j], a[i], bu0, bu1);
                }
            }
        }
        __syncthreads();
    }

    // epilogue: silu(gate)*up -> g_hidden_h
#pragma unroll
    for (int i = 0; i < 2; i++) {
        int rb = m0 + warp_m * 32 + i * 16 + g;
#pragma unroll
        for (int j = 0; j < 2; j++) {
            int n = n0 + warp_n * 16 + j * 8 + 2 * tig;
            if (rb < cnt) {
                size_t base = (size_t)(off + rb) * Id + n;
                float g0 = cg[i][j][0], g1 = cg[i][j][1];
                float h0 = g0 / (1.f + expf(-g0)) * cu[i][j][0];
                float h1 = g1 / (1.f + expf(-g1)) * cu[i][j][1];
                *(__half2*)(g_hidden_h + base) = __floats2half2_rn(h0, h1);
            }
            if (rb + 8 < cnt) {
                size_t base = (size_t)(off + rb + 8) * Id + n;
                float g2 = cg[i][j][2], g3 = cg[i][j][3];
                float h2 = g2 / (1.f + expf(-g2)) * cu[i][j][2];
                float h3 = g3 / (1.f + expf(-g3)) * cu[i][j][3];
                *(__half2*)(g_hidden_h + base) = __floats2half2_rn(h2, h3);
            }
        }
    }
}

// ================= GEMM2 (fp16 MMA): down = hidden @ wd^T =================
// CTA 128m x 128n, K-chunk 64 halves. 512 threads = 16 warps (4m x 4n); warp 32m x 32n.
// 2 CTAs/SM target. Buf: A[128][144] | B[128][144]
#define G2_AB (128 * ROWB)                    // 18432 B
#define G2_BB (128 * ROWB)                    // 18432 B
#define G2_BUFB (G2_AB + G2_BB)               // 36864 B
#define G2_SMEM (2 * G2_BUFB)                 // 73728 B
__global__ void __launch_bounds__(512, 2) k_gemm2() {
    int e   = blockIdx.z;
    int cnt = g_count[e];
    int m0  = blockIdx.x * 128;
    if (m0 >= cnt) return;
    int off = g_offset[e];
    int n0  = blockIdx.y * 128;

    extern __shared__ char smc[];
    char* bufs = smc;

    int tid = threadIdx.x;
    int lane = tid & 31, wid = tid >> 5;
    int warp_m = wid >> 2, warp_n = wid & 3;   // 4 x 4
    int g = lane >> 2, tig = lane & 3;

    const __half* wdE = g_wdh + (size_t)e * Hd * Id;
    // A: 128x8 = 1024 slots (2/thr); B: 1024 slots (2/thr)
    const __half* agm[2]; uint32_t aoff[2];
    const __half* bgm[2]; uint32_t boff[2];
#pragma unroll
    for (int p = 0; p < 2; p++) {
        int idx = tid + 512 * p;
        int r = idx >> 3, q = idx & 7;
        int am = m0 + r; if (am >= cnt) am = cnt - 1;
        agm[p] = g_hidden_h + (size_t)(off + am) * Id + q * 8;
        aoff[p] = r * ROWB + q * 16;
        bgm[p] = wdE + (size_t)(n0 + r) * Id + q * 8;
        boff[p] = G2_AB + r * ROWB + q * 16;
    }
    uint32_t smb = smem_u32(bufs);

    float c[2][4][4] = {};

#pragma unroll
    for (int p = 0; p < 2; p++) { CP16(smb + aoff[p], agm[p]); CP16(smb + boff[p], bgm[p]); }
    cp_commit();

    const int NCH = Id / 64;  // 64
    for (int ch = 0; ch < NCH; ch++) {
        int buf = ch & 1;
        if (ch + 1 < NCH) {
            int k0 = (ch + 1) * 64;
            uint32_t base = smb + (buf ^ 1) * G2_BUFB;
#pragma unroll
            for (int p = 0; p < 2; p++) {
                CP16(base + aoff[p], agm[p] + k0);
                CP16(base + boff[p], bgm[p] + k0);
            }
            cp_commit();
            cp_wait1();
        } else {
            cp_wait0();
        }
        __syncthreads();

        const uint32_t* A = (const uint32_t*)(bufs + buf * G2_BUFB);
        const uint32_t* B = (const uint32_t*)(bufs + buf * G2_BUFB + G2_AB);
#pragma unroll
        for (int kk = 0; kk < 4; kk++) {
            int w0 = kk * 8;
            uint32_t a[2][4];
#pragma unroll
            for (int i = 0; i < 2; i++) {
                int r = warp_m * 32 + i * 16 + g;
                a[i][0] = A[r * 36 + w0 + tig];
                a[i][1] = A[(r + 8) * 36 + w0 + tig];
                a[i][2] = A[r * 36 + w0 + tig + 4];
                a[i][3] = A[(r + 8) * 36 + w0 + tig + 4];
            }
#pragma unroll
            for (int j = 0; j < 4; j++) {
                int n = warp_n * 32 + j * 8 + g;
                uint32_t b0 = B[n * 36 + w0 + tig], b1 = B[n * 36 + w0 + tig + 4];
#pragma unroll
                for (int i = 0; i < 2; i++) MMA_F16(c[i][j], a[i], b0, b1);
            }
        }
        __syncthreads();
    }

#pragma unroll
    for (int i = 0; i < 2; i++) {
        int rb = m0 + warp_m * 32 + i * 16 + g;
#pragma unroll
        for (int j = 0; j < 4; j++) {
            int n = n0 + warp_n * 32 + j * 8 + 2 * tig;
            if (rb < cnt) {
                size_t base = (size_t)(off + rb) * Hd + n;
                g_down[base]     = c[i][j][0];
                g_down[base + 1] = c[i][j][1];
            }
            if (rb + 8 < cnt) {
                size_t base = (size_t)(off + rb + 8) * Hd + n;
                g_down[base]     = c[i][j][2];
                g_down[base + 1] = c[i][j][3];
            }
        }
    }
}

// ---------------- combine ----------------
__global__ void __launch_bounds__(256) k_combine(float* __restrict__ out) {
    int idx = blockIdx.x * 256 + threadIdx.x;
    int t   = idx >> 8;
    int c4  = (idx & 255) << 2;
    int r0  = g_tok_row[t * 2];
    int r1  = g_tok_row[t * 2 + 1];
    float w0 = g_top_w[t * 2];
    float w1 = g_top_w[t * 2 + 1];
    float4 d0 = *(const float4*)(g_down + (size_t)r0 * Hd + c4);
    float4 d1 = *(const float4*)(g_down + (size_t)r1 * Hd + c4);
    float4 o;
    o.x = w0 * d0.x + w1 * d1.x;
    o.y = w0 * d0.y + w1 * d1.y;
    o.z = w0 * d0.z + w1 * d1.z;
    o.w = w0 * d0.w + w1 * d1.w;
    *(float4*)(out + (size_t)t * Hd + c4) = o;
}

// ---------------- launch ----------------
extern "C" void kernel_launch(void* const* d_in, const int* in_sizes, int n_in,
                              void* d_out, int out_size) {
    const float* x  = (const float*)d_in[0];
    const float* gw = (const float*)d_in[1];
    const float* wg = (const float*)d_in[2];
    const float* wu = (const float*)d_in[3];
    const float* wd = (const float*)d_in[4];
    float* out = (float*)d_out;

    cudaFuncSetAttribute(k_gemm1, cudaFuncAttributeMaxDynamicSharedMemorySize, G1_SMEM);
    cudaFuncSetAttribute(k_gemm2, cudaFuncAttributeMaxDynamicSharedMemorySize, G2_SMEM);

    // launch 0: converts + init
    k_prep<<<XB + 3 * WB, 256>>>(x, wg, wu, wd);
    // launch 1: router
    k_router<<<Tn / 8, 256>>>(x, gw);
    // launch 2: assign
    k_assign<<<Tn / 256, 256>>>();

    // launch 3: GEMM1 (ncu profiles launch index 3)
    dim3 g1(64, 32, Ed);
    k_gemm1<<<g1, 512, G1_SMEM>>>();

    // launch 4: GEMM2
    dim3 g2(32, 8, Ed);
    k_gemm2<<<g2, 512, G2_SMEM>>>();

    // launch 5: combine
    k_combine<<<Tn * Hd / 1024, 256>>>(out);
}